// round 1
// baseline (speedup 1.0000x reference)
#include <cuda_runtime.h>

#define IMG_H 512
#define IMG_W 512
#define NBATCH 32
#define RAD 4              // (9-1)/2
#define TS 32              // output tile size
#define PATCH 40           // TS + 2*RAD
#define SP 41              // padded pitch for input patches (conflict-free)
#define HP 33              // padded pitch for h-sum arrays (conflict-free)

__device__ double g_acc;

__global__ void zero_acc_kernel() { g_acc = 0.0; }

__global__ void finalize_kernel(float* out) {
    out[0] = (float)(-g_acc / 8388608.0);   // 32*512*512
}

__global__ __launch_bounds__(256) void cc_kernel(const float* __restrict__ inp,
                                                 const float* __restrict__ tgt) {
    __shared__ float sI[PATCH][SP];
    __shared__ float sT[PATCH][SP];
    __shared__ float hA [PATCH][HP];
    __shared__ float hB [PATCH][HP];
    __shared__ float hAA[PATCH][HP];
    __shared__ float hBB[PATCH][HP];
    __shared__ float hAB[PATCH][HP];
    __shared__ float red[8];

    const int tid = threadIdx.x;
    const int b  = blockIdx.z;
    const int x0 = blockIdx.x << 5;
    const int y0 = blockIdx.y << 5;

    const float* __restrict__ ib = inp + (size_t)b * (IMG_H * IMG_W);
    const float* __restrict__ tb = tgt + (size_t)b * (IMG_H * IMG_W);

    // ---- load haloed patch (zero padding outside image, target rescaled to [0,1]) ----
    for (int idx = tid; idx < PATCH * PATCH; idx += 256) {
        int r = idx / PATCH;
        int c = idx - r * PATCH;
        int gy = y0 + r - RAD;
        int gx = x0 + c - RAD;
        float iv = 0.0f, tv = 0.0f;
        if ((unsigned)gy < IMG_H && (unsigned)gx < IMG_W) {
            int g = gy * IMG_W + gx;
            iv = ib[g];
            tv = (tb[g] + 1.0f) * 0.5f;
        }
        sI[r][c] = iv;
        sT[r][c] = tv;
    }
    __syncthreads();

    // ---- stage 1: horizontal 9-sums of I, T, I*I, T*T, I*T ----
    // 40 rows x 8 runs of 4 outputs = 320 tasks; sliding window of 12 in registers.
    for (int t = tid; t < PATCH * 8; t += 256) {
        const int r  = t >> 3;
        const int c0 = (t & 7) << 2;
        float a[12], bb[12];
        #pragma unroll
        for (int j = 0; j < 12; j++) {
            a[j]  = sI[r][c0 + j];
            bb[j] = sT[r][c0 + j];
        }
        float sA = 0.f, sB = 0.f, sAA = 0.f, sBB = 0.f, sAB = 0.f;
        #pragma unroll
        for (int j = 0; j < 9; j++) {
            sA += a[j];
            sB += bb[j];
            sAA = fmaf(a[j],  a[j],  sAA);
            sBB = fmaf(bb[j], bb[j], sBB);
            sAB = fmaf(a[j],  bb[j], sAB);
        }
        hA [r][c0] = sA;  hB [r][c0] = sB;
        hAA[r][c0] = sAA; hBB[r][c0] = sBB; hAB[r][c0] = sAB;
        #pragma unroll
        for (int o = 1; o < 4; o++) {
            const int ji = o + 8, jo = o - 1;
            sA  += a[ji]  - a[jo];
            sB  += bb[ji] - bb[jo];
            sAA += a[ji]  * a[ji]  - a[jo]  * a[jo];
            sBB += bb[ji] * bb[ji] - bb[jo] * bb[jo];
            sAB += a[ji]  * bb[ji] - a[jo]  * bb[jo];
            hA [r][c0 + o] = sA;  hB [r][c0 + o] = sB;
            hAA[r][c0 + o] = sAA; hBB[r][c0 + o] = sBB; hAB[r][c0 + o] = sAB;
        }
    }
    __syncthreads();

    // ---- stage 2: vertical 9-sums + cc, sliding window of 12 rows per thread ----
    const float inv81 = 1.0f / 81.0f;
    const int tx  = tid & 31;
    const int oy0 = (tid >> 5) << 2;   // 8 runs * 4 rows = 32 rows
    float vA[12], vB[12], vAA[12], vBB[12], vAB[12];
    #pragma unroll
    for (int k = 0; k < 12; k++) {
        vA [k] = hA [oy0 + k][tx];
        vB [k] = hB [oy0 + k][tx];
        vAA[k] = hAA[oy0 + k][tx];
        vBB[k] = hBB[oy0 + k][tx];
        vAB[k] = hAB[oy0 + k][tx];
    }
    float SA = 0.f, SB = 0.f, SAA = 0.f, SBB = 0.f, SAB = 0.f;
    #pragma unroll
    for (int k = 0; k < 9; k++) {
        SA += vA[k]; SB += vB[k]; SAA += vAA[k]; SBB += vBB[k]; SAB += vAB[k];
    }
    float local = 0.0f;
    #pragma unroll
    for (int o = 0; o < 4; o++) {
        float cross = SAB - SA * SB * inv81;
        float tvar  = SBB - SB * SB * inv81;
        float ivar  = SAA - SA * SA * inv81;
        float cc    = __fdividef(cross * cross, tvar * ivar + 1e-5f);
        local += cc;
        if (o < 3) {
            const int ji = o + 9, jo = o;
            SA  += vA [ji] - vA [jo];
            SB  += vB [ji] - vB [jo];
            SAA += vAA[ji] - vAA[jo];
            SBB += vBB[ji] - vBB[jo];
            SAB += vAB[ji] - vAB[jo];
        }
    }

    // ---- block reduction + global accumulate ----
    #pragma unroll
    for (int off = 16; off > 0; off >>= 1)
        local += __shfl_down_sync(0xffffffffu, local, off);
    if ((tid & 31) == 0) red[tid >> 5] = local;
    __syncthreads();
    if (tid < 8) {
        float v = red[tid];
        #pragma unroll
        for (int off = 4; off > 0; off >>= 1)
            v += __shfl_down_sync(0xffu, v, off);
        if (tid == 0) atomicAdd(&g_acc, (double)v);
    }
}

extern "C" void kernel_launch(void* const* d_in, const int* in_sizes, int n_in,
                              void* d_out, int out_size) {
    const float* inp = (const float*)d_in[0];
    const float* tgt = (const float*)d_in[1];
    // d_in[2] is the all-ones 9x9 filter; its effect is baked into the box sums.
    float* out = (float*)d_out;

    zero_acc_kernel<<<1, 1>>>();
    dim3 grid(IMG_W / TS, IMG_H / TS, NBATCH);
    cc_kernel<<<grid, 256>>>(inp, tgt);
    finalize_kernel<<<1, 1>>>(out);
}

// round 2
// speedup vs baseline: 1.1223x; 1.1223x over previous
#include <cuda_runtime.h>

#define H 512
#define W 512
#define NB 32
#define OUTW 24            // output columns per warp (lanes 0..23 produce)
#define STRIPS 22          // ceil(512/24) -> cols 0..527, clipped
#define YSEGS 4
#define YLEN 128           // output rows per warp
#define WARPS_TOTAL (STRIPS * NB * YSEGS)   // 2816
#define NBLOCKS (WARPS_TOTAL / 4)           // 704 blocks of 4 warps

__device__ float g_part[NBLOCKS];
__device__ int   g_cnt = 0;

// 9-wide window sum across lanes: out[l] = v[l] + ... + v[l+8] (valid l<=23)
#define HSUM9(v, out) do {                                   \
    float _s = (v) + __shfl_down_sync(0xffffffffu, (v), 1);  \
    _s += __shfl_down_sync(0xffffffffu, _s, 2);              \
    _s += __shfl_down_sync(0xffffffffu, _s, 4);              \
    (out) = _s + __shfl_down_sync(0xffffffffu, (v), 8);      \
} while (0)

__global__ __launch_bounds__(128) void cc_kernel(const float* __restrict__ inp,
                                                 const float* __restrict__ tgt,
                                                 float* __restrict__ out) {
    const int lane = threadIdx.x & 31;
    const int wid  = threadIdx.x >> 5;
    const int w    = blockIdx.x * 4 + wid;

    const int strip = w % STRIPS;
    const int rem   = w / STRIPS;          // 0..127
    const int b     = rem >> 2;            // 0..31
    const int y0    = (rem & 3) * YLEN;    // 0,128,256,384

    const int x0   = strip * OUTW - 4;     // leftmost loaded column
    const int gx   = x0 + lane;
    const bool cok = (unsigned)gx < W;
    const int ocol = strip * OUTW + lane;
    const bool oval = (lane < OUTW) && (ocol < W);

    const size_t ioff = (size_t)b * (H * W) + (cok ? gx : 0);
    const float* __restrict__ pI = inp + ioff;
    const float* __restrict__ pT = tgt + ioff;

    // vertical ring buffers (9 rows) for the 5 box-summed channels
    float rA[9], rB[9], rAA[9], rBB[9], rAB[9];
    #pragma unroll
    for (int k = 0; k < 9; k++) { rA[k]=0.f; rB[k]=0.f; rAA[k]=0.f; rBB[k]=0.f; rAB[k]=0.f; }
    float SA=0.f, SB=0.f, SAA=0.f, SBB=0.f, SAB=0.f, acc=0.f;

    const float inv81 = 1.0f / 81.0f;

    #pragma unroll 1
    for (int j = 0; j < 16; j++) {
        #pragma unroll
        for (int k = 0; k < 9; k++) {
            const int i  = j * 9 + k;          // 0..143 (need 0..135)
            const int gy = y0 - 4 + i;
            float iv = 0.f, tv = 0.f;
            if (cok && (unsigned)gy < H) {
                iv = __ldg(pI + (size_t)gy * W);
                tv = fmaf(__ldg(pT + (size_t)gy * W), 0.5f, 0.5f);  // rescale to [0,1]
            }
            const float ii = iv * iv;
            const float tt = tv * tv;
            const float it = iv * tv;

            float hA, hB, hAA, hBB, hAB;
            HSUM9(iv, hA);
            HSUM9(tv, hB);
            HSUM9(ii, hAA);
            HSUM9(tt, hBB);
            HSUM9(it, hAB);

            // vertical running 9-sums via ring buffer (slot k == i % 9)
            SA  += hA  - rA [k];  rA [k] = hA;
            SB  += hB  - rB [k];  rB [k] = hB;
            SAA += hAA - rAA[k];  rAA[k] = hAA;
            SBB += hBB - rBB[k];  rBB[k] = hBB;
            SAB += hAB - rAB[k];  rAB[k] = hAB;

            if (i >= 8 && i <= 135 && oval) {
                const float cross = fmaf(-SA * inv81, SB, SAB);
                const float tvar  = fmaf(-SB * inv81, SB, SBB);
                const float ivar  = fmaf(-SA * inv81, SA, SAA);
                acc += __fdividef(cross * cross, fmaf(tvar, ivar, 1e-5f));
            }
        }
    }

    // ---- reduction: warp -> block -> global partials -> last block finishes ----
    #pragma unroll
    for (int off = 16; off > 0; off >>= 1)
        acc += __shfl_down_sync(0xffffffffu, acc, off);

    __shared__ float sred[4];
    __shared__ int   slast;
    if (lane == 0) sred[wid] = acc;
    __syncthreads();
    if (threadIdx.x == 0) {
        g_part[blockIdx.x] = sred[0] + sred[1] + sred[2] + sred[3];
        __threadfence();
        int old = atomicAdd(&g_cnt, 1);
        slast = (old == NBLOCKS - 1) ? 1 : 0;
    }
    __syncthreads();

    if (slast) {
        double d = 0.0;
        for (int idx = threadIdx.x; idx < NBLOCKS; idx += 128)
            d += (double)__ldcg(&g_part[idx]);
        #pragma unroll
        for (int off = 16; off > 0; off >>= 1)
            d += __shfl_down_sync(0xffffffffu, d, off);
        __shared__ double dred[4];
        if (lane == 0) dred[wid] = d;
        __syncthreads();
        if (threadIdx.x == 0) {
            double tot = dred[0] + dred[1] + dred[2] + dred[3];
            out[0] = (float)(-tot / 8388608.0);   // 32*512*512
            g_cnt = 0;                            // reset for next graph replay
        }
    }
}

extern "C" void kernel_launch(void* const* d_in, const int* in_sizes, int n_in,
                              void* d_out, int out_size) {
    const float* inp = (const float*)d_in[0];
    const float* tgt = (const float*)d_in[1];
    // d_in[2] is the all-ones 9x9 filter; baked into the box sums.
    float* out = (float*)d_out;
    cc_kernel<<<NBLOCKS, 128>>>(inp, tgt, out);
}